// round 13
// baseline (speedup 1.0000x reference)
#include <cuda_runtime.h>
#include <cuda_fp16.h>
#include <math_constants.h>

#define NN 50000
#define EE 800000
#define FIN 128
#define HF 256      // HEADS*HID = 4*64
#define GG 256
#define CC 10
#define XN (NN * FIN)
#define W1N (FIN * HF)
#define W2N (HF * HF)

typedef unsigned long long ull;

// ---------------- scratch (no allocations allowed) ----------------
__device__ __half g_Whh[(size_t)NN * HF];   // Wh in fp16 (gather source)
__device__ float g_xtf[XN];                 // tf32-rounded x
__device__ float g_w1tf[W1N];               // tf32-rounded W1
__device__ float g_w2tf[W2N];               // tf32-rounded W2
__device__ float g_out1[(size_t)NN * HF];   // layer1 out (tf32-rounded)
__device__ float g_out2[(size_t)NN * HF];
__device__ float g_ls[NN * 4];
__device__ float g_ld[NN * 4];
__device__ int   g_deg[NN];
__device__ int   g_rowptr[NN + 1];
__device__ int   g_cursor[NN];
__device__ int   g_srcs[EE];
__device__ float g_mx[GG * HF];
__device__ float g_sm[GG * HF];
__device__ int   g_cnt[GG];

__device__ __forceinline__ unsigned f16x2_of(float lo, float hi) {
    unsigned r;
    asm("cvt.rn.f16x2.f32 %0, %1, %2;" : "=r"(r) : "f"(hi), "f"(lo));  // first src -> high half
    return r;
}
__device__ __forceinline__ float2 h2f(unsigned u) {
    __half2 h = *reinterpret_cast<__half2*>(&u);
    return __half22float2(h);
}
__device__ __forceinline__ float tf32r(float f) {
    unsigned r;
    asm("cvt.rna.tf32.f32 %0, %1;" : "=r"(r) : "f"(f));
    return __uint_as_float(r);
}
__device__ __forceinline__ void mma_tf32(float* c, const unsigned* a, const unsigned* b) {
    asm("mma.sync.aligned.m16n8k8.row.col.f32.tf32.tf32.f32 "
        "{%0,%1,%2,%3}, {%4,%5,%6,%7}, {%8,%9}, {%0,%1,%2,%3};"
        : "+f"(c[0]), "+f"(c[1]), "+f"(c[2]), "+f"(c[3])
        : "r"(a[0]), "r"(a[1]), "r"(a[2]), "r"(a[3]), "r"(b[0]), "r"(b[1]));
}
__device__ __forceinline__ void cp16(void* smem_dst, const void* gsrc) {
    unsigned s = (unsigned)__cvta_generic_to_shared(smem_dst);
    asm volatile("cp.async.cg.shared.global [%0], [%1], 16;" :: "r"(s), "l"(gsrc));
}
__device__ __forceinline__ void cp_commit() { asm volatile("cp.async.commit_group;"); }
__device__ __forceinline__ void cp_wait1() { asm volatile("cp.async.wait_group 1;"); }
__device__ __forceinline__ void cp_wait0() { asm volatile("cp.async.wait_group 0;"); }

// ---------------- init + tf32 pre-round (one pass) ----------------
__global__ void initprep_kernel(const float* __restrict__ x,
                                const float* __restrict__ W1,
                                const float* __restrict__ W2) {
    int i = blockIdx.x * blockDim.x + threadIdx.x;
    if (i < XN) g_xtf[i] = tf32r(x[i]);
    if (i < W1N) g_w1tf[i] = tf32r(W1[i]);
    if (i < W2N) g_w2tf[i] = tf32r(W2[i]);
    if (i < NN) g_deg[i] = 0;
    if (i < GG * HF) { g_mx[i] = -CUDART_INF_F; g_sm[i] = 0.f; }
    if (i < GG) g_cnt[i] = 0;
}

// ---------------- CSR build ----------------
__global__ void count_kernel(const int* __restrict__ ei) {
    int e = blockIdx.x * blockDim.x + threadIdx.x;
    if (e >= EE) return;
    atomicAdd(&g_deg[ei[EE + e]], 1);
}

__global__ void scan_kernel() {
    const int T = 1024;
    int tid = threadIdx.x;
    int per = (NN + T - 1) / T;
    int start = tid * per;
    int end = start + per; if (end > NN) end = NN; if (start > NN) start = NN;
    int s = 0;
    for (int i = start; i < end; i++) s += g_deg[i];
    __shared__ int sums[T];
    sums[tid] = s;
    __syncthreads();
    for (int off = 1; off < T; off <<= 1) {
        int v = (tid >= off) ? sums[tid - off] : 0;
        __syncthreads();
        sums[tid] += v;
        __syncthreads();
    }
    int run = (tid > 0) ? sums[tid - 1] : 0;
    for (int i = start; i < end; i++) {
        g_rowptr[i] = run;
        g_cursor[i] = run;
        run += g_deg[i];
    }
    if (tid == T - 1) g_rowptr[NN] = run;
}

__global__ void scatter_kernel(const int* __restrict__ ei) {
    int e = blockIdx.x * blockDim.x + threadIdx.x;
    if (e >= EE) return;
    int dst = ei[EE + e];
    int pos = atomicAdd(&g_cursor[dst], 1);
    g_srcs[pos] = ei[e];
}

// ---- GEMM (tf32 tensor core, pre-rounded operands) + fused logits ----
// Whh[M,256] = fp16(A[M,K]*B[K,256]); 8 warps as 4(m)x2(n), warp tile 32x64.
#define LDA 36
#define LDB 136
#define GEMM_SMEM ((2 * 128 * LDA + 2 * 32 * LDB) * 4 + 2 * 128 * 4)
template <int K>
__global__ __launch_bounds__(256, 2)
void gemm_fused_kernel(const float* __restrict__ A, const float* __restrict__ B,
                       __half* __restrict__ Whh,
                       const float* __restrict__ a_src, const float* __restrict__ a_dst,
                       int M) {
    constexpr int BM = 128, BN = 128, BK = 32;
    constexpr int T = K / BK;
    extern __shared__ __align__(16) char smem_raw[];
    float* AsBase = (float*)smem_raw;                 // 2 x BM x LDA
    float* BsBase = AsBase + 2 * BM * LDA;            // 2 x BK x LDB
    float* s_as = BsBase + 2 * BK * LDB;
    float* s_ad = s_as + BN;

    int tid = threadIdx.x;
    int lane = tid & 31, w = tid >> 5;
    int wm = w >> 1, wn = w & 1;
    int g = lane >> 2, tig = lane & 3;
    int m0 = blockIdx.y * BM, n0 = blockIdx.x * BN;   // n0 in {0,128}
    if (tid < BN) { s_as[tid] = a_src[n0 + tid]; s_ad[tid] = a_dst[n0 + tid]; }

    float c[2][8][4];
#pragma unroll
    for (int tm = 0; tm < 2; tm++)
#pragma unroll
        for (int tn = 0; tn < 8; tn++)
#pragma unroll
            for (int j = 0; j < 4; j++) c[tm][tn][j] = 0.f;

    auto issue = [&](int st, int k0) {
        float* Ast = AsBase + st * BM * LDA;
        float* Bst = BsBase + st * BK * LDB;
#pragma unroll
        for (int u = 0; u < 4; u++) {
            int ch = tid + u * 256;                  // 0..1023
            int m = ch >> 3, kq = (ch & 7) * 4;      // A: 128 rows x 8 chunks
            int gm = m0 + m; if (gm >= M) gm = M - 1;
            cp16(Ast + m * LDA + kq, &A[(size_t)gm * K + k0 + kq]);
            int r = ch >> 5, cq = (ch & 31) * 4;     // B: 32 rows x 32 chunks
            cp16(Bst + r * LDB + cq, &B[(size_t)(k0 + r) * 256 + n0 + cq]);
        }
        cp_commit();
    };

    issue(0, 0);

#pragma unroll 1
    for (int t = 0; t < T; t++) {
        int st = t & 1;
        if (t + 1 < T) { issue(st ^ 1, (t + 1) * BK); cp_wait1(); }
        else           { cp_wait0(); }
        __syncthreads();
        float* Ast = AsBase + st * BM * LDA;
        float* Bst = BsBase + st * BK * LDB;
#pragma unroll
        for (int ks = 0; ks < BK / 8; ks++) {
            unsigned af[2][4], bf[8][2];
#pragma unroll
            for (int tm = 0; tm < 2; tm++) {
                int r0 = (wm * 32 + tm * 16 + g) * LDA + ks * 8 + tig;
                af[tm][0] = __float_as_uint(Ast[r0]);
                af[tm][1] = __float_as_uint(Ast[r0 + 8 * LDA]);
                af[tm][2] = __float_as_uint(Ast[r0 + 4]);
                af[tm][3] = __float_as_uint(Ast[r0 + 8 * LDA + 4]);
            }
#pragma unroll
            for (int tn = 0; tn < 8; tn++) {
                int nb = (ks * 8 + tig) * LDB + wn * 64 + tn * 8 + g;
                bf[tn][0] = __float_as_uint(Bst[nb]);
                bf[tn][1] = __float_as_uint(Bst[nb + 4 * LDB]);
            }
#pragma unroll
            for (int tm = 0; tm < 2; tm++)
#pragma unroll
                for (int tn = 0; tn < 8; tn++)
                    mma_tf32(c[tm][tn], af[tm], bf[tn]);
        }
        __syncthreads();
    }

    // ---- epilogue: fp16 Whh store + fused ls/ld ----
    int h = (n0 >> 6) + wn;   // head owned by this warp
#pragma unroll
    for (int tm = 0; tm < 2; tm++) {
        int rA = m0 + wm * 32 + tm * 16 + g;
        int rB = rA + 8;
        float lsA = 0.f, ldA = 0.f, lsB = 0.f, ldB = 0.f;
#pragma unroll
        for (int tn = 0; tn < 8; tn++) {
            int col = wn * 64 + tn * 8 + tig * 2;
            float c0 = c[tm][tn][0], c1 = c[tm][tn][1];
            float c2 = c[tm][tn][2], c3 = c[tm][tn][3];
            if (rA < M) *(unsigned*)&Whh[(size_t)rA * 256 + n0 + col] = f16x2_of(c0, c1);
            if (rB < M) *(unsigned*)&Whh[(size_t)rB * 256 + n0 + col] = f16x2_of(c2, c3);
            lsA += c0 * s_as[col] + c1 * s_as[col + 1];
            ldA += c0 * s_ad[col] + c1 * s_ad[col + 1];
            lsB += c2 * s_as[col] + c3 * s_as[col + 1];
            ldB += c2 * s_ad[col] + c3 * s_ad[col + 1];
        }
#pragma unroll
        for (int off = 1; off <= 2; off <<= 1) {
            lsA += __shfl_xor_sync(0xffffffffu, lsA, off);
            ldA += __shfl_xor_sync(0xffffffffu, ldA, off);
            lsB += __shfl_xor_sync(0xffffffffu, lsB, off);
            ldB += __shfl_xor_sync(0xffffffffu, ldB, off);
        }
        if (tig == 0) {
            if (rA < M) { g_ls[rA * 4 + h] = lsA; g_ld[rA * 4 + h] = ldA; }
            if (rB < M) { g_ls[rB * 4 + h] = lsB; g_ld[rB * 4 + h] = ldB; }
        }
    }
}

// ---- fused edge-softmax + aggregation + ELU (warp per dst) ----
// ROUND: tf32-round output (when it feeds the next tf32 GEMM).
__device__ __forceinline__ void acc_edge(float* acc, float ph, uint4 w) {
    float2 f0 = h2f(w.x), f1 = h2f(w.y), f2 = h2f(w.z), f3 = h2f(w.w);
    acc[0] = fmaf(ph, f0.x, acc[0]); acc[1] = fmaf(ph, f0.y, acc[1]);
    acc[2] = fmaf(ph, f1.x, acc[2]); acc[3] = fmaf(ph, f1.y, acc[3]);
    acc[4] = fmaf(ph, f2.x, acc[4]); acc[5] = fmaf(ph, f2.y, acc[5]);
    acc[6] = fmaf(ph, f3.x, acc[6]); acc[7] = fmaf(ph, f3.y, acc[7]);
}

template <bool ROUND>
__global__ __launch_bounds__(256, 4)
void agg_kernel(const __half* __restrict__ Whh, float* __restrict__ out) {
    int warp = (blockIdx.x * blockDim.x + threadIdx.x) >> 5;
    int lane = threadIdx.x & 31;
    if (warp >= NN) return;
    int n = warp;
    int start = g_rowptr[n], end = g_rowptr[n + 1];
    int hsel = lane >> 3;
    float dnh = g_ld[n * 4 + hsel];

    float acc[8];
#pragma unroll
    for (int j = 0; j < 8; j++) acc[j] = 0.f;
    float zh = 0.f;

    int i = start;
    for (; i + 3 < end; i += 4) {
        int s[4];
#pragma unroll
        for (int u = 0; u < 4; u++) s[u] = g_srcs[i + u];
        uint4 w[4];
#pragma unroll
        for (int u = 0; u < 4; u++)
            w[u] = *(const uint4*)(Whh + (size_t)s[u] * HF + lane * 8);
#pragma unroll
        for (int u = 0; u < 4; u++) {
            float e = g_ls[s[u] * 4 + hsel] + dnh;
            float p = __expf(fmaxf(e, 0.01f * e));
            zh += p;
            acc_edge(acc, p, w[u]);
        }
    }
    for (; i < end; i++) {
        int s = g_srcs[i];
        float e = g_ls[s * 4 + hsel] + dnh;
        uint4 w = *(const uint4*)(Whh + (size_t)s * HF + lane * 8);
        float p = __expf(fmaxf(e, 0.01f * e));
        zh += p;
        acc_edge(acc, p, w);
    }
    float inv = 1.f / (zh + 1e-16f);
    float res[8];
#pragma unroll
    for (int j = 0; j < 8; j++) {
        float v = acc[j] * inv;
        v = v > 0.f ? v : (__expf(v) - 1.f);  // ELU
        res[j] = ROUND ? tf32r(v) : v;
    }
    float* o = out + (size_t)n * HF + lane * 8;
    *(float4*)o = make_float4(res[0], res[1], res[2], res[3]);
    *(float4*)(o + 4) = make_float4(res[4], res[5], res[6], res[7]);
}

// ---------------- segmented pooling (batch is sorted) ----------------
#define PN 128
__device__ __forceinline__ void pool_flush(int g, int f, float mx, float sm) {
    if (mx > -CUDART_INF_F) {
        int* amx = (int*)&g_mx[g * HF + f];
        if (mx >= 0.f) atomicMax(amx, __float_as_int(mx));
        else atomicMin((unsigned int*)amx, (unsigned int)__float_as_int(mx));
        atomicAdd(&g_sm[g * HF + f], sm);
    }
}
__global__ __launch_bounds__(256)
void pool_kernel(const float* __restrict__ x, const int* __restrict__ batch) {
    __shared__ int sb[PN];
    int b0 = blockIdx.x * PN;
    int cnt = NN - b0; if (cnt > PN) cnt = PN;
    for (int i = threadIdx.x; i < cnt; i += 256) sb[i] = batch[b0 + i];
    __syncthreads();
    int f = threadIdx.x;
    int g = sb[0];
    float mx = -CUDART_INF_F, sm = 0.f;
    int segc = 0;
    for (int i = 0; i < cnt; i++) {
        int gb = sb[i];
        if (gb != g) {
            pool_flush(g, f, mx, sm);
            if (f == 0) atomicAdd(&g_cnt[g], segc);
            g = gb; mx = -CUDART_INF_F; sm = 0.f; segc = 0;
        }
        float v = x[(size_t)(b0 + i) * HF + f];
        mx = fmaxf(mx, v); sm += v; segc++;
    }
    pool_flush(g, f, mx, sm);
    if (f == 0) atomicAdd(&g_cnt[g], segc);
}

// ---------------- finalize pool + linear ----------------
__global__ void final_kernel(const float* __restrict__ linW, const float* __restrict__ linb,
                             float* __restrict__ outp) {
    int t = blockIdx.x * blockDim.x + threadIdx.x;
    if (t >= GG * CC) return;
    int g = t / CC, c = t % CC;
    float cnt = fmaxf((float)g_cnt[g], 1.f);
    float inv = 1.f / cnt;
    float acc = linb[c];
    const float* mxr = g_mx + g * HF;
    const float* smr = g_sm + g * HF;
#pragma unroll 4
    for (int f = 0; f < HF; f++) {
        float mv = mxr[f];
        if (!isfinite(mv)) mv = 0.f;
        acc = fmaf(mv, linW[f * CC + c], acc);
    }
#pragma unroll 4
    for (int f = 0; f < HF; f++) {
        acc = fmaf(smr[f] * inv, linW[(HF + f) * CC + c], acc);
    }
    outp[t] = acc;
}

// ---------------- launch ----------------
extern "C" void kernel_launch(void* const* d_in, const int* in_sizes, int n_in,
                              void* d_out, int out_size) {
    const float* x      = (const float*)d_in[0];
    const int*   ei     = (const int*)d_in[1];
    const int*   batch  = (const int*)d_in[2];
    const float* a1s    = (const float*)d_in[4];
    const float* a1d    = (const float*)d_in[5];
    const float* a2s    = (const float*)d_in[7];
    const float* a2d    = (const float*)d_in[8];
    const float* linW   = (const float*)d_in[9];
    const float* linb   = (const float*)d_in[10];
    float* outp = (float*)d_out;

    __half* pWhh; cudaGetSymbolAddress((void**)&pWhh, g_Whh);
    float* pXtf;  cudaGetSymbolAddress((void**)&pXtf,  g_xtf);
    float* pW1tf; cudaGetSymbolAddress((void**)&pW1tf, g_w1tf);
    float* pW2tf; cudaGetSymbolAddress((void**)&pW2tf, g_w2tf);
    float* pO1;   cudaGetSymbolAddress((void**)&pO1,   g_out1);
    float* pO2;   cudaGetSymbolAddress((void**)&pO2,   g_out2);

    static int attr_done = 0;
    if (!attr_done) {
        cudaFuncSetAttribute(gemm_fused_kernel<FIN>,
                             cudaFuncAttributeMaxDynamicSharedMemorySize, GEMM_SMEM);
        cudaFuncSetAttribute(gemm_fused_kernel<HF>,
                             cudaFuncAttributeMaxDynamicSharedMemorySize, GEMM_SMEM);
        attr_done = 1;
    }

    dim3 g1(2, (NN + 127) / 128);
    int aggBlocks = (NN * 32 + 255) / 256;

    initprep_kernel<<<(XN + 255) / 256, 256>>>(x, (const float*)d_in[3], (const float*)d_in[6]);
    count_kernel<<<(EE + 255) / 256, 256>>>(ei);
    scan_kernel<<<1, 1024>>>();
    gemm_fused_kernel<FIN><<<g1, 256, GEMM_SMEM>>>(pXtf, pW1tf, pWhh, a1s, a1d, NN);  // profiled slot
    scatter_kernel<<<(EE + 255) / 256, 256>>>(ei);
    agg_kernel<true><<<aggBlocks, 256>>>(pWhh, pO1);

    gemm_fused_kernel<HF><<<g1, 256, GEMM_SMEM>>>(pO1, pW2tf, pWhh, a2s, a2d, NN);
    agg_kernel<false><<<aggBlocks, 256>>>(pWhh, pO2);

    pool_kernel<<<(NN + PN - 1) / PN, 256>>>(pO2, batch);
    final_kernel<<<(GG * CC + 255) / 256, 256>>>(linW, linb, outp);
}

// round 14
// speedup vs baseline: 1.0848x; 1.0848x over previous
#include <cuda_runtime.h>
#include <cuda_fp16.h>
#include <math_constants.h>

#define NN 50000
#define EE 800000
#define FIN 128
#define HF 256      // HEADS*HID = 4*64
#define GG 256
#define CC 10
#define W1N (FIN * HF)
#define W2N (HF * HF)

typedef unsigned long long ull;

// ---------------- scratch (no allocations allowed) ----------------
__device__ __half g_Whh[(size_t)NN * HF];   // Wh in fp16 (gather source)
__device__ float g_w1tf[W1N];               // tf32-rounded W1
__device__ float g_w2tf[W2N];               // tf32-rounded W2
__device__ float g_out1[(size_t)NN * HF];   // layer1 out (tf32-rounded)
__device__ float g_out2[(size_t)NN * HF];
__device__ float g_ls[NN * 4];
__device__ float g_ld[NN * 4];
__device__ int   g_deg[NN];
__device__ int   g_rowptr[NN + 1];
__device__ int   g_cursor[NN];
__device__ int   g_srcs[EE];
__device__ float g_mx[GG * HF];
__device__ float g_sm[GG * HF];
__device__ int   g_cnt[GG];

__device__ __forceinline__ unsigned f16x2_of(float lo, float hi) {
    unsigned r;
    asm("cvt.rn.f16x2.f32 %0, %1, %2;" : "=r"(r) : "f"(hi), "f"(lo));  // first src -> high half
    return r;
}
__device__ __forceinline__ float2 h2f(unsigned u) {
    __half2 h = *reinterpret_cast<__half2*>(&u);
    return __half22float2(h);
}
__device__ __forceinline__ float tf32r(float f) {
    unsigned r;
    asm("cvt.rna.tf32.f32 %0, %1;" : "=r"(r) : "f"(f));
    return __uint_as_float(r);
}
__device__ __forceinline__ unsigned tf32_of(float f) {
    unsigned r;
    asm("cvt.rna.tf32.f32 %0, %1;" : "=r"(r) : "f"(f));
    return r;
}
__device__ __forceinline__ void mma_tf32(float* c, const unsigned* a, const unsigned* b) {
    asm("mma.sync.aligned.m16n8k8.row.col.f32.tf32.tf32.f32 "
        "{%0,%1,%2,%3}, {%4,%5,%6,%7}, {%8,%9}, {%0,%1,%2,%3};"
        : "+f"(c[0]), "+f"(c[1]), "+f"(c[2]), "+f"(c[3])
        : "r"(a[0]), "r"(a[1]), "r"(a[2]), "r"(a[3]), "r"(b[0]), "r"(b[1]));
}
__device__ __forceinline__ void cp16(void* smem_dst, const void* gsrc) {
    unsigned s = (unsigned)__cvta_generic_to_shared(smem_dst);
    asm volatile("cp.async.cg.shared.global [%0], [%1], 16;" :: "r"(s), "l"(gsrc));
}
__device__ __forceinline__ void cp_commit() { asm volatile("cp.async.commit_group;"); }
__device__ __forceinline__ void cp_wait1() { asm volatile("cp.async.wait_group 1;"); }
__device__ __forceinline__ void cp_wait0() { asm volatile("cp.async.wait_group 0;"); }

// ---------------- init + weight tf32 pre-round (small) ----------------
__global__ void initprep_kernel(const float* __restrict__ W1, const float* __restrict__ W2) {
    int i = blockIdx.x * blockDim.x + threadIdx.x;
    if (i < W1N) g_w1tf[i] = tf32r(W1[i]);
    if (i < W2N) g_w2tf[i] = tf32r(W2[i]);
    if (i < NN) g_deg[i] = 0;
    if (i < GG * HF) { g_mx[i] = -CUDART_INF_F; g_sm[i] = 0.f; }
    if (i < GG) g_cnt[i] = 0;
}

// ---------------- CSR build ----------------
__global__ void count_kernel(const int* __restrict__ ei) {
    int e = blockIdx.x * blockDim.x + threadIdx.x;
    if (e >= EE) return;
    atomicAdd(&g_deg[ei[EE + e]], 1);
}

__global__ void scan_kernel() {
    const int T = 1024;
    int tid = threadIdx.x;
    int per = (NN + T - 1) / T;
    int start = tid * per;
    int end = start + per; if (end > NN) end = NN; if (start > NN) start = NN;
    int s = 0;
    for (int i = start; i < end; i++) s += g_deg[i];
    __shared__ int sums[T];
    sums[tid] = s;
    __syncthreads();
    for (int off = 1; off < T; off <<= 1) {
        int v = (tid >= off) ? sums[tid - off] : 0;
        __syncthreads();
        sums[tid] += v;
        __syncthreads();
    }
    int run = (tid > 0) ? sums[tid - 1] : 0;
    for (int i = start; i < end; i++) {
        g_rowptr[i] = run;
        g_cursor[i] = run;
        run += g_deg[i];
    }
    if (tid == T - 1) g_rowptr[NN] = run;
}

__global__ void scatter_kernel(const int* __restrict__ ei) {
    int e = blockIdx.x * blockDim.x + threadIdx.x;
    if (e >= EE) return;
    int dst = ei[EE + e];
    int pos = atomicAdd(&g_cursor[dst], 1);
    g_srcs[pos] = ei[e];
}

// ---- GEMM (tf32 tensor core) + fused logits: Whh[M,256] = fp16(A[M,K]*B[K,256]) ----
// 8 warps as 4(m)x2(n); warp tile 32x64. B always pre-rounded; A cvt iff CVTA.
#define LDA 36
#define LDB 136
#define GEMM_SMEM ((2 * 128 * LDA + 2 * 32 * LDB) * 4 + 2 * 128 * 4)
template <int K, bool CVTA>
__global__ __launch_bounds__(256, 2)
void gemm_fused_kernel(const float* __restrict__ A, const float* __restrict__ B,
                       __half* __restrict__ Whh,
                       const float* __restrict__ a_src, const float* __restrict__ a_dst,
                       int M) {
    constexpr int BM = 128, BN = 128, BK = 32;
    constexpr int T = K / BK;
    extern __shared__ __align__(16) char smem_raw[];
    float* AsBase = (float*)smem_raw;                 // 2 x BM x LDA
    float* BsBase = AsBase + 2 * BM * LDA;            // 2 x BK x LDB
    float* s_as = BsBase + 2 * BK * LDB;
    float* s_ad = s_as + BN;

    int tid = threadIdx.x;
    int lane = tid & 31, w = tid >> 5;
    int wm = w >> 1, wn = w & 1;
    int g = lane >> 2, tig = lane & 3;
    int m0 = blockIdx.y * BM, n0 = blockIdx.x * BN;   // n0 in {0,128}
    if (tid < BN) { s_as[tid] = a_src[n0 + tid]; s_ad[tid] = a_dst[n0 + tid]; }

    float c[2][8][4];
#pragma unroll
    for (int tm = 0; tm < 2; tm++)
#pragma unroll
        for (int tn = 0; tn < 8; tn++)
#pragma unroll
            for (int j = 0; j < 4; j++) c[tm][tn][j] = 0.f;

    auto issue = [&](int st, int k0) {
        float* Ast = AsBase + st * BM * LDA;
        float* Bst = BsBase + st * BK * LDB;
#pragma unroll
        for (int u = 0; u < 4; u++) {
            int ch = tid + u * 256;                  // 0..1023
            int m = ch >> 3, kq = (ch & 7) * 4;      // A: 128 rows x 8 chunks
            int gm = m0 + m; if (gm >= M) gm = M - 1;
            cp16(Ast + m * LDA + kq, &A[(size_t)gm * K + k0 + kq]);
            int r = ch >> 5, cq = (ch & 31) * 4;     // B: 32 rows x 32 chunks
            cp16(Bst + r * LDB + cq, &B[(size_t)(k0 + r) * 256 + n0 + cq]);
        }
        cp_commit();
    };

    issue(0, 0);

#pragma unroll 1
    for (int t = 0; t < T; t++) {
        int st = t & 1;
        if (t + 1 < T) { issue(st ^ 1, (t + 1) * BK); cp_wait1(); }
        else           { cp_wait0(); }
        __syncthreads();
        float* Ast = AsBase + st * BM * LDA;
        float* Bst = BsBase + st * BK * LDB;
#pragma unroll
        for (int ks = 0; ks < BK / 8; ks++) {
            unsigned af[2][4], bf[8][2];
#pragma unroll
            for (int tm = 0; tm < 2; tm++) {
                int r0 = (wm * 32 + tm * 16 + g) * LDA + ks * 8 + tig;
                if (CVTA) {
                    af[tm][0] = tf32_of(Ast[r0]);
                    af[tm][1] = tf32_of(Ast[r0 + 8 * LDA]);
                    af[tm][2] = tf32_of(Ast[r0 + 4]);
                    af[tm][3] = tf32_of(Ast[r0 + 8 * LDA + 4]);
                } else {
                    af[tm][0] = __float_as_uint(Ast[r0]);
                    af[tm][1] = __float_as_uint(Ast[r0 + 8 * LDA]);
                    af[tm][2] = __float_as_uint(Ast[r0 + 4]);
                    af[tm][3] = __float_as_uint(Ast[r0 + 8 * LDA + 4]);
                }
            }
#pragma unroll
            for (int tn = 0; tn < 8; tn++) {
                int nb = (ks * 8 + tig) * LDB + wn * 64 + tn * 8 + g;
                bf[tn][0] = __float_as_uint(Bst[nb]);
                bf[tn][1] = __float_as_uint(Bst[nb + 4 * LDB]);
            }
#pragma unroll
            for (int tm = 0; tm < 2; tm++)
#pragma unroll
                for (int tn = 0; tn < 8; tn++)
                    mma_tf32(c[tm][tn], af[tm], bf[tn]);
        }
        __syncthreads();
    }

    // ---- epilogue: fp16 Whh store + fused ls/ld ----
    int h = (n0 >> 6) + wn;   // head owned by this warp
#pragma unroll
    for (int tm = 0; tm < 2; tm++) {
        int rA = m0 + wm * 32 + tm * 16 + g;
        int rB = rA + 8;
        float lsA = 0.f, ldA = 0.f, lsB = 0.f, ldB = 0.f;
#pragma unroll
        for (int tn = 0; tn < 8; tn++) {
            int col = wn * 64 + tn * 8 + tig * 2;
            float c0 = c[tm][tn][0], c1 = c[tm][tn][1];
            float c2 = c[tm][tn][2], c3 = c[tm][tn][3];
            if (rA < M) *(unsigned*)&Whh[(size_t)rA * 256 + n0 + col] = f16x2_of(c0, c1);
            if (rB < M) *(unsigned*)&Whh[(size_t)rB * 256 + n0 + col] = f16x2_of(c2, c3);
            lsA += c0 * s_as[col] + c1 * s_as[col + 1];
            ldA += c0 * s_ad[col] + c1 * s_ad[col + 1];
            lsB += c2 * s_as[col] + c3 * s_as[col + 1];
            ldB += c2 * s_ad[col] + c3 * s_ad[col + 1];
        }
#pragma unroll
        for (int off = 1; off <= 2; off <<= 1) {
            lsA += __shfl_xor_sync(0xffffffffu, lsA, off);
            ldA += __shfl_xor_sync(0xffffffffu, ldA, off);
            lsB += __shfl_xor_sync(0xffffffffu, lsB, off);
            ldB += __shfl_xor_sync(0xffffffffu, ldB, off);
        }
        if (tig == 0) {
            if (rA < M) { g_ls[rA * 4 + h] = lsA; g_ld[rA * 4 + h] = ldA; }
            if (rB < M) { g_ls[rB * 4 + h] = lsB; g_ld[rB * 4 + h] = ldB; }
        }
    }
}

// ---- fused edge-softmax + aggregation + ELU (warp per dst) ----
// R12 structure (8-edge batched loads); ROUND = tf32-round output for next GEMM.
__device__ __forceinline__ void acc_edge(float* acc, float ph, uint4 w) {
    float2 f0 = h2f(w.x), f1 = h2f(w.y), f2 = h2f(w.z), f3 = h2f(w.w);
    acc[0] = fmaf(ph, f0.x, acc[0]); acc[1] = fmaf(ph, f0.y, acc[1]);
    acc[2] = fmaf(ph, f1.x, acc[2]); acc[3] = fmaf(ph, f1.y, acc[3]);
    acc[4] = fmaf(ph, f2.x, acc[4]); acc[5] = fmaf(ph, f2.y, acc[5]);
    acc[6] = fmaf(ph, f3.x, acc[6]); acc[7] = fmaf(ph, f3.y, acc[7]);
}

template <bool ROUND>
__global__ __launch_bounds__(256)
void agg_kernel(const __half* __restrict__ Whh, float* __restrict__ out) {
    int warp = (blockIdx.x * blockDim.x + threadIdx.x) >> 5;
    int lane = threadIdx.x & 31;
    if (warp >= NN) return;
    int n = warp;
    int start = g_rowptr[n], end = g_rowptr[n + 1];
    int hsel = lane >> 3;
    float dnh = g_ld[n * 4 + hsel];

    float acc[8];
#pragma unroll
    for (int j = 0; j < 8; j++) acc[j] = 0.f;
    float zh = 0.f;

    int i = start;
    for (; i + 7 < end; i += 8) {
        int s[8];
#pragma unroll
        for (int u = 0; u < 8; u++) s[u] = g_srcs[i + u];
        uint4 w[8];
#pragma unroll
        for (int u = 0; u < 8; u++)
            w[u] = *(const uint4*)(Whh + (size_t)s[u] * HF + lane * 8);
        float e[8];
#pragma unroll
        for (int u = 0; u < 8; u++) e[u] = g_ls[s[u] * 4 + hsel] + dnh;
#pragma unroll
        for (int u = 0; u < 8; u++) {
            float p = __expf(fmaxf(e[u], 0.01f * e[u]));
            zh += p;
            acc_edge(acc, p, w[u]);
        }
    }
    for (; i + 3 < end; i += 4) {
        int s[4];
#pragma unroll
        for (int u = 0; u < 4; u++) s[u] = g_srcs[i + u];
        uint4 w[4];
#pragma unroll
        for (int u = 0; u < 4; u++)
            w[u] = *(const uint4*)(Whh + (size_t)s[u] * HF + lane * 8);
#pragma unroll
        for (int u = 0; u < 4; u++) {
            float e = g_ls[s[u] * 4 + hsel] + dnh;
            float p = __expf(fmaxf(e, 0.01f * e));
            zh += p;
            acc_edge(acc, p, w[u]);
        }
    }
    for (; i < end; i++) {
        int s = g_srcs[i];
        float e = g_ls[s * 4 + hsel] + dnh;
        uint4 w = *(const uint4*)(Whh + (size_t)s * HF + lane * 8);
        float p = __expf(fmaxf(e, 0.01f * e));
        zh += p;
        acc_edge(acc, p, w);
    }
    float inv = 1.f / (zh + 1e-16f);
    float res[8];
#pragma unroll
    for (int j = 0; j < 8; j++) {
        float v = acc[j] * inv;
        v = v > 0.f ? v : (__expf(v) - 1.f);  // ELU
        res[j] = ROUND ? tf32r(v) : v;
    }
    float* o = out + (size_t)n * HF + lane * 8;
    *(float4*)o = make_float4(res[0], res[1], res[2], res[3]);
    *(float4*)(o + 4) = make_float4(res[4], res[5], res[6], res[7]);
}

// ---------------- segmented pooling (batch is sorted) ----------------
#define PN 128
__device__ __forceinline__ void pool_flush(int g, int f, float mx, float sm) {
    if (mx > -CUDART_INF_F) {
        int* amx = (int*)&g_mx[g * HF + f];
        if (mx >= 0.f) atomicMax(amx, __float_as_int(mx));
        else atomicMin((unsigned int*)amx, (unsigned int)__float_as_int(mx));
        atomicAdd(&g_sm[g * HF + f], sm);
    }
}
__global__ __launch_bounds__(256)
void pool_kernel(const float* __restrict__ x, const int* __restrict__ batch) {
    __shared__ int sb[PN];
    int b0 = blockIdx.x * PN;
    int cnt = NN - b0; if (cnt > PN) cnt = PN;
    for (int i = threadIdx.x; i < cnt; i += 256) sb[i] = batch[b0 + i];
    __syncthreads();
    int f = threadIdx.x;
    int g = sb[0];
    float mx = -CUDART_INF_F, sm = 0.f;
    int segc = 0;
    for (int i = 0; i < cnt; i++) {
        int gb = sb[i];
        if (gb != g) {
            pool_flush(g, f, mx, sm);
            if (f == 0) atomicAdd(&g_cnt[g], segc);
            g = gb; mx = -CUDART_INF_F; sm = 0.f; segc = 0;
        }
        float v = x[(size_t)(b0 + i) * HF + f];
        mx = fmaxf(mx, v); sm += v; segc++;
    }
    pool_flush(g, f, mx, sm);
    if (f == 0) atomicAdd(&g_cnt[g], segc);
}

// ---------------- finalize pool + linear ----------------
__global__ void final_kernel(const float* __restrict__ linW, const float* __restrict__ linb,
                             float* __restrict__ outp) {
    int t = blockIdx.x * blockDim.x + threadIdx.x;
    if (t >= GG * CC) return;
    int g = t / CC, c = t % CC;
    float cnt = fmaxf((float)g_cnt[g], 1.f);
    float inv = 1.f / cnt;
    float acc = linb[c];
    const float* mxr = g_mx + g * HF;
    const float* smr = g_sm + g * HF;
#pragma unroll 4
    for (int f = 0; f < HF; f++) {
        float mv = mxr[f];
        if (!isfinite(mv)) mv = 0.f;
        acc = fmaf(mv, linW[f * CC + c], acc);
    }
#pragma unroll 4
    for (int f = 0; f < HF; f++) {
        acc = fmaf(smr[f] * inv, linW[(HF + f) * CC + c], acc);
    }
    outp[t] = acc;
}

// ---------------- launch ----------------
extern "C" void kernel_launch(void* const* d_in, const int* in_sizes, int n_in,
                              void* d_out, int out_size) {
    const float* x      = (const float*)d_in[0];
    const int*   ei     = (const int*)d_in[1];
    const int*   batch  = (const int*)d_in[2];
    const float* a1s    = (const float*)d_in[4];
    const float* a1d    = (const float*)d_in[5];
    const float* a2s    = (const float*)d_in[7];
    const float* a2d    = (const float*)d_in[8];
    const float* linW   = (const float*)d_in[9];
    const float* linb   = (const float*)d_in[10];
    float* outp = (float*)d_out;

    __half* pWhh; cudaGetSymbolAddress((void**)&pWhh, g_Whh);
    float* pW1tf; cudaGetSymbolAddress((void**)&pW1tf, g_w1tf);
    float* pW2tf; cudaGetSymbolAddress((void**)&pW2tf, g_w2tf);
    float* pO1;   cudaGetSymbolAddress((void**)&pO1,   g_out1);
    float* pO2;   cudaGetSymbolAddress((void**)&pO2,   g_out2);

    static int attr_done = 0;
    if (!attr_done) {
        cudaFuncSetAttribute(gemm_fused_kernel<FIN, true>,
                             cudaFuncAttributeMaxDynamicSharedMemorySize, GEMM_SMEM);
        cudaFuncSetAttribute(gemm_fused_kernel<HF, false>,
                             cudaFuncAttributeMaxDynamicSharedMemorySize, GEMM_SMEM);
        attr_done = 1;
    }

    dim3 g1(2, (NN + 127) / 128);
    int aggBlocks = (NN * 32 + 255) / 256;
    int initN = GG * HF;   // 65536 >= W2N, W1N, NN, GG

    initprep_kernel<<<(initN + 255) / 256, 256>>>((const float*)d_in[3], (const float*)d_in[6]);
    count_kernel<<<(EE + 255) / 256, 256>>>(ei);
    scan_kernel<<<1, 1024>>>();
    gemm_fused_kernel<FIN, true><<<g1, 256, GEMM_SMEM>>>(x, pW1tf, pWhh, a1s, a1d, NN);  // profiled slot
    scatter_kernel<<<(EE + 255) / 256, 256>>>(ei);
    agg_kernel<true><<<aggBlocks, 256>>>(pWhh, pO1);

    gemm_fused_kernel<HF, false><<<g1, 256, GEMM_SMEM>>>(pO1, pW2tf, pWhh, a2s, a2d, NN);
    agg_kernel<false><<<aggBlocks, 256>>>(pWhh, pO2);

    pool_kernel<<<(NN + PN - 1) / PN, 256>>>(pO2, batch);
    final_kernel<<<(GG * CC + 255) / 256, 256>>>(linW, linb, outp);
}